// round 17
// baseline (speedup 1.0000x reference)
#include <cuda_runtime.h>
#include <cuda_fp16.h>
#include <mma.h>
#include <cstdint>

using namespace nvcuda;

#define NNODES 50000
#define NEDGES 400000
#define DDIM   512
#define NCAT   1024
#define NEG_SLOPE 0.01f
#define FILL 2.0f

// ---------------------------------------------------------------------------
// Device scratch (static: no allocations allowed)
// ---------------------------------------------------------------------------
__device__ __half g_Bh[(size_t)DDIM * NCAT];        // fp16 [W | Wres] (1MB)
__device__ __half g_Hh[(size_t)3 * NNODES * DDIM];  // H_t = X_t @ W (fp16)
__device__ float  g_deg[NNODES];
__device__ float  g_dis[NNODES];
__device__ int    g_cnt[NNODES];
__device__ int    g_off[NNODES + 1];
__device__ int    g_bsum[128];
__device__ int    g_srcs[NEDGES];
__device__ float  g_coef[NEDGES];

struct alignas(8) half4 { __half2 a, b; };

// ---------------------------------------------------------------------------
// Weight fp16 conversion (1MB, one-shot)
// ---------------------------------------------------------------------------
__global__ void conv_b_kernel(const float* __restrict__ W, const float* __restrict__ Wres) {
    int i = blockIdx.x * blockDim.x + threadIdx.x;
    if (i >= DDIM * NCAT) return;
    int k = i >> 10, n = i & 1023;
    float v = (n < DDIM) ? W[(size_t)k * DDIM + n] : Wres[(size_t)k * DDIM + (n - DDIM)];
    g_Bh[i] = __float2half_rn(v);
}

// ---------------------------------------------------------------------------
// Degree / norm / CSR build
// ---------------------------------------------------------------------------
__global__ void init_kernel() {
    int n = blockIdx.x * blockDim.x + threadIdx.x;
    if (n < NNODES) { g_deg[n] = FILL; g_cnt[n] = 0; }
}
__global__ void accum_kernel(const int* __restrict__ dst, const float* __restrict__ w) {
    int e = blockIdx.x * blockDim.x + threadIdx.x;
    if (e < NEDGES) {
        int d = dst[e];
        atomicAdd(&g_deg[d], w[e]);
        atomicAdd(&g_cnt[d], 1);
    }
}
__global__ void calc_dis_kernel() {
    int n = blockIdx.x * blockDim.x + threadIdx.x;
    if (n < NNODES) {
        float d = g_deg[n];
        g_dis[n] = (d > 0.0f) ? rsqrtf(d) : 0.0f;
    }
}

#define SCAN_BS 512
#define SCAN_NB ((NNODES + SCAN_BS - 1) / SCAN_BS)   // 98

__global__ void scan1_kernel() {
    __shared__ int s[SCAN_BS];
    int tid = threadIdx.x;
    int i = blockIdx.x * SCAN_BS + tid;
    int val = (i < NNODES) ? g_cnt[i] : 0;
    s[tid] = val;
    __syncthreads();
    #pragma unroll
    for (int o = 1; o < SCAN_BS; o <<= 1) {
        int t = (tid >= o) ? s[tid - o] : 0;
        __syncthreads();
        s[tid] += t;
        __syncthreads();
    }
    int incl = s[tid];
    if (i < NNODES) g_off[i] = incl - val;
    if (tid == SCAN_BS - 1) g_bsum[blockIdx.x] = incl;
}
__global__ void scan2_kernel() {
    if (threadIdx.x == 0) {
        int run = 0;
        for (int b = 0; b < SCAN_NB; b++) { int t = g_bsum[b]; g_bsum[b] = run; run += t; }
    }
}
__global__ void scan3_kernel() {
    int i = blockIdx.x * blockDim.x + threadIdx.x;
    if (i < NNODES) { g_off[i] += g_bsum[i >> 9]; g_cnt[i] = 0; }
    if (i == 0) g_off[NNODES] = NEDGES;
}
__global__ void fill_kernel(const int* __restrict__ src, const int* __restrict__ dst,
                            const float* __restrict__ w) {
    int e = blockIdx.x * blockDim.x + threadIdx.x;
    if (e >= NEDGES) return;
    int s = src[e], d = dst[e];
    int pos = atomicAdd(&g_cnt[d], 1);
    int slot = g_off[d] + pos;
    g_srcs[slot] = s;
    g_coef[slot] = g_dis[s] * w[e] * g_dis[d];
}

// ---------------------------------------------------------------------------
// A-resident FP16 WMMA GEMM (fp32 accumulate).
// CTA = 64 rows x full N=1024; A read once -> resident fp16 smem; B streamed
// via 2-stage prefetch-distance-1 cp.async ring, BK=32.
// R17 additions:
//   (a) A fragments (ks=0) of chunk kc+1 are register-prefetched during
//       chunk kc's MMAs (A is resident; manual hoist across the barrier).
//   (b) The next n-tile's B chunk 0 is prefetched into stage 0 BEFORE the
//       epilogue; the epilogue stages exclusively through the stage-1
//       region, so cp.async overlaps the epilogue smem traffic.
// Warp grid 2x4, warp tile 32x64. 2 CTAs/SM (smem 100.3KB).
// ---------------------------------------------------------------------------
#define MT 64
#define NT 256
#define BK 32
#define LDA 520             // halves per A row (1040B)
#define LDB 264             // halves per B chunk row (528B)
#define LDC 260             // f32 staging stride (1040B)
#define A_BYTES (MT * LDA * 2)          // 66560
#define B_STAGE (BK * LDB)              // 8448 halves = 16896 B
#define SMEM_BYTES (A_BYTES + 2 * B_STAGE * 2)   // 100352
#define NCHUNK (DDIM / BK)              // 16 per N-tile
#define NITER (NCAT / NT)               // 4

__global__ __launch_bounds__(256, 2) void gemm_fp16_wmma_kernel(
    const float* __restrict__ X0,
    const float* __restrict__ X1,
    const float* __restrict__ X2,
    float* __restrict__ Obase,       // [3, M, 512] (d_out)
    int M)
{
    extern __shared__ char smem_raw[];
    __half* As = (__half*)smem_raw;                           // resident A
    __half* Bs = (__half*)(smem_raw + A_BYTES);               // 2 B stages
    float*  sC = (float*)(smem_raw + A_BYTES + B_STAGE * 2);  // staging = stage-1 region

    const int tid = threadIdx.x;
    const int wid = tid >> 5;
    const int m0 = blockIdx.x * MT;
    const int t = blockIdx.y;

    const float* A = (t == 0) ? X0 : (t == 1) ? X1 : X2;
    const size_t slice = (size_t)M * DDIM;

    const int wm = wid & 1;     // 2 row strips of 32
    const int wn = wid >> 1;    // 4 col strips of 64

    // ---- A prologue: 64 rows x 512 fp32 = 8192 float4, 32 per thread ----
    #pragma unroll 8
    for (int i = 0; i < 32; i++) {
        int idx = i * 256 + tid;
        int r = idx >> 7, c4 = idx & 127;     // 128 float4 per row
        int gr = (m0 + r < M) ? (m0 + r) : (M - 1);
        float4 v = __ldg((const float4*)(A + (size_t)gr * DDIM) + c4);
        half4 h;
        h.a = __floats2half2_rn(v.x, v.y);
        h.b = __floats2half2_rn(v.z, v.w);
        *(half4*)(As + r * LDA + c4 * 4) = h;
    }
    __syncthreads();

    auto load_b = [&](int ncol0, int kc, int st) {
        const int k0 = kc * BK;
        __half* b_base = Bs + st * B_STAGE;
        #pragma unroll
        for (int i = 0; i < 4; i++) {
            int idx = i * 256 + tid;
            int r = idx >> 5, c = idx & 31;
            const __half* src = g_Bh + (size_t)(k0 + r) * NCAT + ncol0 + c * 8;
            uint32_t dst;
            asm("{ .reg .u64 t; cvta.to.shared.u64 t, %1; cvt.u32.u64 %0, t; }"
                : "=r"(dst) : "l"(b_base + r * LDB + c * 8));
            asm volatile("cp.async.cg.shared.global [%0], [%1], 16;"
                         :: "r"(dst), "l"(src));
        }
        asm volatile("cp.async.commit_group;" ::: "memory");
    };

    // B chunk 0 of the first n-tile
    load_b(0, 0, 0);

    #pragma unroll 1
    for (int ni_t = 0; ni_t < NITER; ni_t++) {
        const int ncol0 = ni_t * NT;

        wmma::fragment<wmma::accumulator, 16, 16, 16, float> acc[2][4];
        #pragma unroll
        for (int mi = 0; mi < 2; mi++)
            #pragma unroll
            for (int ni = 0; ni < 4; ni++) wmma::fill_fragment(acc[mi][ni], 0.0f);

        // A frags for chunk 0, kstep 0 (A is resident; no barrier needed)
        wmma::fragment<wmma::matrix_a, 16, 16, 16, __half, wmma::row_major> af0[2];
        #pragma unroll
        for (int mi = 0; mi < 2; mi++)
            wmma::load_matrix_sync(af0[mi], As + (wm * 32 + mi * 16) * LDA, LDA);

        #pragma unroll 1
        for (int kc = 0; kc < NCHUNK; kc++) {
            asm volatile("cp.async.wait_group 0;" ::: "memory");  // chunk kc ready
            __syncthreads();
            if (kc + 1 < NCHUNK) load_b(ncol0, kc + 1, (kc + 1) & 1);

            const __half* a_base = As + kc * BK;
            const __half* b_base = Bs + (kc & 1) * B_STAGE;

            // kstep 0: A frags already in registers (af0)
            {
                wmma::fragment<wmma::matrix_b, 16, 16, 16, __half, wmma::row_major> bf[4];
                #pragma unroll
                for (int ni = 0; ni < 4; ni++)
                    wmma::load_matrix_sync(bf[ni], b_base + wn * 64 + ni * 16, LDB);
                #pragma unroll
                for (int mi = 0; mi < 2; mi++)
                    #pragma unroll
                    for (int ni = 0; ni < 4; ni++)
                        wmma::mma_sync(acc[mi][ni], af0[mi], bf[ni], acc[mi][ni]);
            }
            // kstep 1
            {
                wmma::fragment<wmma::matrix_a, 16, 16, 16, __half, wmma::row_major> af1[2];
                wmma::fragment<wmma::matrix_b, 16, 16, 16, __half, wmma::row_major> bf[4];
                #pragma unroll
                for (int mi = 0; mi < 2; mi++)
                    wmma::load_matrix_sync(af1[mi],
                        a_base + (wm * 32 + mi * 16) * LDA + 16, LDA);
                #pragma unroll
                for (int ni = 0; ni < 4; ni++)
                    wmma::load_matrix_sync(bf[ni],
                        b_base + 16 * LDB + wn * 64 + ni * 16, LDB);
                #pragma unroll
                for (int mi = 0; mi < 2; mi++)
                    #pragma unroll
                    for (int ni = 0; ni < 4; ni++)
                        wmma::mma_sync(acc[mi][ni], af1[mi], bf[ni], acc[mi][ni]);
            }
            // register-prefetch A frags (ks=0) of chunk kc+1 (resident A)
            if (kc + 1 < NCHUNK) {
                const __half* a_next = As + (kc + 1) * BK;
                #pragma unroll
                for (int mi = 0; mi < 2; mi++)
                    wmma::load_matrix_sync(af0[mi],
                        a_next + (wm * 32 + mi * 16) * LDA, LDA);
            }
        }
        __syncthreads();   // B ring drained & all warps done

        // prefetch the NEXT n-tile's B chunk 0 into stage 0 (overlaps epilogue;
        // epilogue stages only through the stage-1 region)
        if (ni_t + 1 < NITER) load_b(ncol0 + NT, 0, 0);

        const bool is_h = (ncol0 < DDIM);
        const int oc0 = ncol0 & (DDIM - 1);

        if (is_h || m0 + MT > M) {
            __half* Ht = g_Hh + (size_t)t * slice;
            float* outbase = Obase + t * slice;
            #pragma unroll
            for (int s = 0; s < 4; s++) {
                if (wm == (s >> 1)) {
                    int mi = s & 1;
                    #pragma unroll
                    for (int ni = 0; ni < 4; ni++)
                        wmma::store_matrix_sync(sC + wn * 64 + ni * 16,
                                                acc[mi][ni], LDC,
                                                wmma::mem_row_major);
                }
                __syncthreads();
                #pragma unroll
                for (int i = 0; i < 4; i++) {
                    int idx = i * 256 + tid;
                    int r = idx >> 6, c = idx & 63;
                    int gr = m0 + s * 16 + r;
                    if (gr < M) {
                        float4 v = *(const float4*)(sC + r * LDC + c * 4);
                        if (is_h) {
                            half4 h;
                            h.a = __floats2half2_rn(v.x, v.y);
                            h.b = __floats2half2_rn(v.z, v.w);
                            *(half4*)(Ht + (size_t)gr * DDIM + oc0 + c * 4) = h;
                        } else {
                            *(float4*)(outbase + (size_t)gr * DDIM + oc0 + c * 4) = v;
                        }
                    }
                }
                __syncthreads();
            }
        } else {
            float* outbase = Obase + t * slice;
            #pragma unroll
            for (int mi = 0; mi < 2; mi++)
                #pragma unroll
                for (int ni = 0; ni < 4; ni++) {
                    int r = m0 + wm * 32 + mi * 16;
                    int c = oc0 + wn * 64 + ni * 16;
                    wmma::store_matrix_sync(outbase + (size_t)r * DDIM + c,
                                            acc[mi][ni], DDIM, wmma::mem_row_major);
                }
            __syncthreads();
        }
    }
}

// ---------------------------------------------------------------------------
// Fused gather + self-loop + residual + leaky relu, fp16 H.
// Flat 1D grid ordered t-major so each conv's 51MB H slice stays L2-resident.
// ---------------------------------------------------------------------------
__device__ __forceinline__ void acc_row(const __half* row, int c, float cf,
                                        float& x, float& y, float& z, float& w) {
    half4 v = ((const half4*)row)[c];
    float2 lo = __half22float2(v.a);
    float2 hi = __half22float2(v.b);
    x = fmaf(cf, lo.x, x); y = fmaf(cf, lo.y, y);
    z = fmaf(cf, hi.x, z); w = fmaf(cf, hi.y, w);
}

__global__ __launch_bounds__(128) void gather_finalize_kernel(float* __restrict__ Obase) {
    const int bid = blockIdx.x;
    const int t = bid / NNODES;
    const int n = bid - t * NNODES;
    const int c = threadIdx.x;              // 4-col group index 0..127

    const size_t slice = (size_t)NNODES * DDIM;
    const __half* Ht = g_Hh + t * slice;
    float* O = Obase + t * slice;

    const float dn = g_dis[n];
    const float sc = FILL * dn * dn;

    float ax = 0.f, ay = 0.f, az = 0.f, aw = 0.f;
    float bx = 0.f, by = 0.f, bz = 0.f, bw = 0.f;
    acc_row(Ht + (size_t)n * DDIM, c, sc, ax, ay, az, aw);

    const int beg = g_off[n], end = g_off[n + 1];
    int j = beg;
    for (; j + 1 < end; j += 2) {
        int s0 = g_srcs[j], s1 = g_srcs[j + 1];
        float c0 = g_coef[j], c1 = g_coef[j + 1];
        acc_row(Ht + (size_t)s0 * DDIM, c, c0, ax, ay, az, aw);
        acc_row(Ht + (size_t)s1 * DDIM, c, c1, bx, by, bz, bw);
    }
    if (j < end)
        acc_row(Ht + (size_t)g_srcs[j] * DDIM, c, g_coef[j], ax, ay, az, aw);

    ax += bx; ay += by; az += bz; aw += bw;

    float4* op = (float4*)(O + (size_t)n * DDIM) + c;
    float4 o = *op;
    o.x = o.x + ax; o.x = o.x >= 0.f ? o.x : NEG_SLOPE * o.x;
    o.y = o.y + ay; o.y = o.y >= 0.f ? o.y : NEG_SLOPE * o.y;
    o.z = o.z + az; o.z = o.z >= 0.f ? o.z : NEG_SLOPE * o.z;
    o.w = o.w + aw; o.w = o.w >= 0.f ? o.w : NEG_SLOPE * o.w;
    *op = o;
}

// ---------------------------------------------------------------------------
// Launch (GEMM at launch index 3 so ncu's fixed skip keeps capturing it)
// ---------------------------------------------------------------------------
extern "C" void kernel_launch(void* const* d_in, const int* in_sizes, int n_in,
                              void* d_out, int out_size)
{
    const float* x0   = (const float*)d_in[0];
    const float* x1   = (const float*)d_in[1];
    const float* x2   = (const float*)d_in[2];
    const int*   adj  = (const int*)d_in[3];
    const float* w    = (const float*)d_in[4];
    const float* Wmat = (const float*)d_in[5];
    const float* Wres = (const float*)d_in[6];
    float* out = (float*)d_out;

    const int* src = adj;
    const int* dst = adj + NEDGES;

    cudaFuncSetAttribute(gemm_fp16_wmma_kernel,
                         cudaFuncAttributeMaxDynamicSharedMemorySize, SMEM_BYTES);

    // 0: weights to fp16
    conv_b_kernel<<<(DDIM * NCAT + 255) / 256, 256>>>(Wmat, Wres);
    // 1-2: independent prep
    init_kernel<<<(NNODES + 255) / 256, 256>>>();
    accum_kernel<<<(NEDGES + 255) / 256, 256>>>(dst, w);

    // 3: A-resident GEMM, [H_t | O_t] = X_t @ [W | Wres]
    dim3 gemm_grid((NNODES + MT - 1) / MT, 3);   // (782, 3)
    gemm_fp16_wmma_kernel<<<gemm_grid, 256, SMEM_BYTES>>>(x0, x1, x2, out, NNODES);

    // 4-8: norm + CSR build
    calc_dis_kernel<<<(NNODES + 255) / 256, 256>>>();
    scan1_kernel<<<SCAN_NB, SCAN_BS>>>();
    scan2_kernel<<<1, 32>>>();
    scan3_kernel<<<(NNODES + 255) / 256, 256>>>();
    fill_kernel<<<(NEDGES + 255) / 256, 256>>>(src, dst, w);

    // 9: batched gather/finalize, t-major for L2 residency of each H slice
    gather_finalize_kernel<<<3 * NNODES, 128>>>(out);
}